// round 1
// baseline (speedup 1.0000x reference)
#include <cuda_runtime.h>
#include <cuda_bf16.h>
#include <math.h>

// ----- problem constants -----
#define E_TOTAL 800000
#define NN      50000
#define DIN     64
#define EIN     32
#define EMIN    160   // 2*DIN + EIN
#define HID     128
#define EOUT    64
#define NMIN    128   // EOUT + DIN
#define DOUT    64

#define TE      32    // edges/nodes per tile
#define PITCH   34    // smem row pitch (even -> 8B-aligned float2, conflict-free)

// ----- scratch (static device globals; no allocation at runtime) -----
__device__ float g_logits[E_TOTAL];
__device__ float g_ex[E_TOTAL];
__device__ float g_m[NN];
__device__ float g_denom[NN];
__device__ float g_agg[(size_t)NN * EOUT];

// ----- packed f32x2 FMA (sm_103a) -----
union F2 { float2 f; unsigned long long u; };

__device__ __forceinline__ void fma2(F2& acc, F2 x, F2 w) {
    asm("fma.rn.f32x2 %0, %1, %2, %0;" : "+l"(acc.u) : "l"(x.u), "l"(w.u));
}

__device__ __forceinline__ void atomicMaxFloat(float* addr, float v) {
    if (v >= 0.0f) atomicMax((int*)addr, __float_as_int(v));
    else           atomicMin((unsigned int*)addr, __float_as_uint(v));
}

// ============================================================
// K0: init scratch
// ============================================================
__global__ void init_kernel() {
    int idx = blockIdx.x * blockDim.x + threadIdx.x;   // grid covers NN*64
    g_agg[idx] = 0.0f;
    if (idx < NN) {
        g_m[idx] = __int_as_float(0xff800000);  // -inf
        g_denom[idx] = 0.0f;
    }
}

// ============================================================
// K1: fused edge MLP + attention logits
//   32 edges per block, 128 threads
// ============================================================
__global__ __launch_bounds__(128) void edge_kernel(
    const float* __restrict__ nf, const float* __restrict__ ef,
    const int* __restrict__ src, const int* __restrict__ dst,
    const float* __restrict__ We1, const float* __restrict__ be1,
    const float* __restrict__ We2, const float* __restrict__ be2,
    const float* __restrict__ Wa1, const float* __restrict__ ba1,
    const float* __restrict__ Wa2, const float* __restrict__ ba2,
    float* __restrict__ uh_e)
{
    __shared__ float s_x[EMIN * PITCH];   // 160*34 floats = 21760B (aliased as s_he later)
    __shared__ float s_ha[HID * PITCH];   // 128*34 floats = 17408B
    __shared__ int   s_src[TE];
    __shared__ int   s_dst[TE];

    const int tid = threadIdx.x;
    const int e0  = blockIdx.x * TE;      // E_TOTAL % TE == 0, no tail

    if (tid < TE) {
        s_src[tid] = src[e0 + tid];
        s_dst[tid] = dst[e0 + tid];
    }
    __syncthreads();

    // ---- gather e_in transposed: s_x[k][e] ----
    {
        const int e  = tid & 31;
        const int kq = tid >> 5;          // 0..3
        const int rs = s_src[e];
        const int rd = s_dst[e];
        const float4* nf4 = (const float4*)nf;
        const float4* ef4 = (const float4*)ef;
        #pragma unroll
        for (int kk = kq; kk < 40; kk += 4) {  // 40 float4 rows of 160-wide input
            float4 v;
            if (kk < 16)      v = nf4[(size_t)rs * 16 + kk];
            else if (kk < 32) v = nf4[(size_t)rd * 16 + (kk - 16)];
            else              v = ef4[(size_t)(e0 + e) * 8 + (kk - 32)];
            const int k = kk * 4;
            s_x[(k + 0) * PITCH + e] = v.x;
            s_x[(k + 1) * PITCH + e] = v.y;
            s_x[(k + 2) * PITCH + e] = v.z;
            s_x[(k + 3) * PITCH + e] = v.w;
        }
    }
    __syncthreads();

    // ---- layer 1: thread j = tid computes hidden unit j for all 32 edges ----
    F2 he[16], ha[16];
    {
        float b = be1[tid];
        #pragma unroll
        for (int i = 0; i < 16; i++) { he[i].f = make_float2(b, b); }
        b = ba1[tid];
        #pragma unroll
        for (int i = 0; i < 16; i++) { ha[i].f = make_float2(b, b); }
    }
    #pragma unroll 2
    for (int k = 0; k < EMIN; k++) {
        const float w1 = __ldg(&We1[k * HID + tid]);
        const float w2 = __ldg(&Wa1[k * HID + tid]);
        F2 we, wa;
        we.f = make_float2(w1, w1);
        wa.f = make_float2(w2, w2);
        const float* row = &s_x[k * PITCH];
        #pragma unroll
        for (int i = 0; i < 16; i++) {
            F2 x; x.f = *(const float2*)&row[2 * i];
            fma2(he[i], x, we);
            fma2(ha[i], x, wa);
        }
    }

    __syncthreads();                // all reads of s_x done before aliasing
    float* s_he = s_x;              // alias: [HID][PITCH] fits in s_x

    #pragma unroll
    for (int i = 0; i < 16; i++) {
        float2 v = he[i].f;
        v.x = fmaxf(v.x, 0.0f); v.y = fmaxf(v.y, 0.0f);
        *(float2*)&s_he[tid * PITCH + 2 * i] = v;
        float2 u = ha[i].f;
        u.x = fmaxf(u.x, 0.0f); u.y = fmaxf(u.y, 0.0f);
        *(float2*)&s_ha[tid * PITCH + 2 * i] = u;
    }
    __syncthreads();

    // ---- layer 2 (edge model): thread -> (output col o, 16-edge half) ----
    {
        const int o     = tid & 63;
        const int half  = tid >> 6;
        const int ebase = half * 16;
        F2 acc[8];
        const float b2 = be2[o];
        #pragma unroll
        for (int i = 0; i < 8; i++) acc[i].f = make_float2(b2, b2);

        #pragma unroll 2
        for (int j = 0; j < HID; j++) {
            const float w = __ldg(&We2[j * EOUT + o]);
            F2 w2; w2.f = make_float2(w, w);
            const float* row = &s_he[j * PITCH + ebase];
            #pragma unroll
            for (int i = 0; i < 8; i++) {
                F2 x; x.f = *(const float2*)&row[2 * i];
                fma2(acc[i], x, w2);
            }
        }
        float* outp = uh_e + (size_t)e0 * EOUT;
        #pragma unroll
        for (int i = 0; i < 8; i++) {
            outp[(size_t)(ebase + 2 * i)     * EOUT + o] = acc[i].f.x;
            outp[(size_t)(ebase + 2 * i + 1) * EOUT + o] = acc[i].f.y;
        }
    }

    // ---- attention logit: threads 0..31 each handle one edge ----
    if (tid < TE) {
        float acc = ba2[0];
        #pragma unroll 4
        for (int j = 0; j < HID; j++)
            acc += s_ha[j * PITCH + tid] * __ldg(&Wa2[j]);
        g_logits[e0 + tid] = acc;
        atomicMaxFloat(&g_m[s_dst[tid]], acc);
    }
}

// ============================================================
// K2: ex = exp(logit - m[dst]); denom[dst] += ex
// ============================================================
__global__ void softmax_kernel(const int* __restrict__ dst) {
    int e = blockIdx.x * blockDim.x + threadIdx.x;   // grid covers E exactly
    int d = dst[e];
    float ex = expf(g_logits[e] - g_m[d]);
    g_ex[e] = ex;
    atomicAdd(&g_denom[d], ex);
}

// ============================================================
// K3: agg[dst] += uh_e * attn   (one thread per (edge, feature))
// ============================================================
__global__ void agg_kernel(const int* __restrict__ dst,
                           const float* __restrict__ uh_e) {
    size_t idx = (size_t)blockIdx.x * blockDim.x + threadIdx.x;  // E*64 exactly
    int e = (int)(idx >> 6);
    int j = (int)(idx & 63);
    int d = dst[e];
    float w = g_ex[e] / fmaxf(g_denom[d], 1e-38f);
    atomicAdd(&g_agg[(size_t)d * EOUT + j], uh_e[idx] * w);
}

// ============================================================
// K4: node MLP on concat(agg, nf)
// ============================================================
__global__ __launch_bounds__(128) void node_kernel(
    const float* __restrict__ nf,
    const float* __restrict__ Wn1, const float* __restrict__ bn1,
    const float* __restrict__ Wn2, const float* __restrict__ bn2,
    float* __restrict__ uh_n)
{
    __shared__ float s_x[NMIN * PITCH];  // 128*34 = 17408B (aliased as s_h later)

    const int tid = threadIdx.x;
    const int n0  = blockIdx.x * TE;

    // ---- gather concat(agg, nf) transposed ----
    {
        const int e  = tid & 31;
        const int kq = tid >> 5;
        const int n  = n0 + e;
        const bool ok = (n < NN);
        const float4* ag4 = (const float4*)g_agg;
        const float4* nf4 = (const float4*)nf;
        #pragma unroll
        for (int kk = kq; kk < 32; kk += 4) {
            float4 v = make_float4(0.f, 0.f, 0.f, 0.f);
            if (ok) {
                if (kk < 16) v = ag4[(size_t)n * 16 + kk];
                else         v = nf4[(size_t)n * 16 + (kk - 16)];
            }
            const int k = kk * 4;
            s_x[(k + 0) * PITCH + e] = v.x;
            s_x[(k + 1) * PITCH + e] = v.y;
            s_x[(k + 2) * PITCH + e] = v.z;
            s_x[(k + 3) * PITCH + e] = v.w;
        }
    }
    __syncthreads();

    // ---- layer 1 ----
    F2 h[16];
    {
        float b = bn1[tid];
        #pragma unroll
        for (int i = 0; i < 16; i++) h[i].f = make_float2(b, b);
    }
    #pragma unroll 2
    for (int k = 0; k < NMIN; k++) {
        const float w1 = __ldg(&Wn1[k * HID + tid]);
        F2 w; w.f = make_float2(w1, w1);
        const float* row = &s_x[k * PITCH];
        #pragma unroll
        for (int i = 0; i < 16; i++) {
            F2 x; x.f = *(const float2*)&row[2 * i];
            fma2(h[i], x, w);
        }
    }
    __syncthreads();
    float* s_h = s_x;   // alias, same size
    #pragma unroll
    for (int i = 0; i < 16; i++) {
        float2 v = h[i].f;
        v.x = fmaxf(v.x, 0.0f); v.y = fmaxf(v.y, 0.0f);
        *(float2*)&s_h[tid * PITCH + 2 * i] = v;
    }
    __syncthreads();

    // ---- layer 2 ----
    {
        const int o     = tid & 63;
        const int half  = tid >> 6;
        const int ebase = half * 16;
        F2 acc[8];
        const float b2 = bn2[o];
        #pragma unroll
        for (int i = 0; i < 8; i++) acc[i].f = make_float2(b2, b2);

        #pragma unroll 2
        for (int j = 0; j < HID; j++) {
            const float w = __ldg(&Wn2[j * DOUT + o]);
            F2 w2; w2.f = make_float2(w, w);
            const float* row = &s_h[j * PITCH + ebase];
            #pragma unroll
            for (int i = 0; i < 8; i++) {
                F2 x; x.f = *(const float2*)&row[2 * i];
                fma2(acc[i], x, w2);
            }
        }
        #pragma unroll
        for (int i = 0; i < 8; i++) {
            int na = n0 + ebase + 2 * i;
            int nb = na + 1;
            if (na < NN) uh_n[(size_t)na * DOUT + o] = acc[i].f.x;
            if (nb < NN) uh_n[(size_t)nb * DOUT + o] = acc[i].f.y;
        }
    }
}

// ============================================================
extern "C" void kernel_launch(void* const* d_in, const int* in_sizes, int n_in,
                              void* d_out, int out_size) {
    const float* nf  = (const float*)d_in[0];
    const float* ef  = (const float*)d_in[1];
    const int*   src = (const int*)d_in[2];
    const int*   dst = (const int*)d_in[3];
    const float* We1 = (const float*)d_in[4];
    const float* be1 = (const float*)d_in[5];
    const float* We2 = (const float*)d_in[6];
    const float* be2 = (const float*)d_in[7];
    const float* Wa1 = (const float*)d_in[8];
    const float* ba1 = (const float*)d_in[9];
    const float* Wa2 = (const float*)d_in[10];
    const float* ba2 = (const float*)d_in[11];
    const float* Wn1 = (const float*)d_in[12];
    const float* bn1 = (const float*)d_in[13];
    const float* Wn2 = (const float*)d_in[14];
    const float* bn2 = (const float*)d_in[15];

    float* out  = (float*)d_out;
    float* uh_n = out;                                // [NN, DOUT]
    float* uh_e = out + (size_t)NN * DOUT;            // [E, EOUT]

    init_kernel<<<(NN * 64) / 256, 256>>>();
    edge_kernel<<<E_TOTAL / TE, 128>>>(nf, ef, src, dst,
                                       We1, be1, We2, be2,
                                       Wa1, ba1, Wa2, ba2, uh_e);
    softmax_kernel<<<E_TOTAL / 256, 256>>>(dst);
    agg_kernel<<<(E_TOTAL * 64) / 256, 256>>>(dst, uh_e);
    node_kernel<<<(NN + TE - 1) / TE, 128>>>(nf, Wn1, bn1, Wn2, bn2, uh_n);
}

// round 6
// speedup vs baseline: 2.1530x; 2.1530x over previous
#include <cuda_runtime.h>
#include <cuda_bf16.h>
#include <math.h>
#include <stdint.h>

// ----- problem constants -----
#define E_TOTAL 800000
#define NN      50000
#define DIN     64
#define EIN     32
#define EMIN    160
#define HID     128
#define EOUT    64
#define NMIN    128
#define DOUT    64

#define TILE    128
#define NTILES  (E_TOTAL / TILE)   // 6250
#define GRID_P  148

#define TE      32
#define PITCH   34

// ----- scratch -----
__device__ float g_logits[E_TOTAL];
__device__ float g_ex[E_TOTAL];
__device__ float g_m[NN];
__device__ float g_denom[NN];
__device__ float g_agg[(size_t)NN * EOUT];

// ----- smem layouts (bytes) -----
// X (A-frag SoA): 4 planes * 5121 floats = 81936 -> pad 81952
#define XPLANE   5121
#define HPLANE   4097
#define SM_X     0
#define SM_B1    81952
#define SM_B2    (SM_B1 + 81920)           // kernel E only
#define SM_BE1   (SM_B2 + 32768)
#define SM_BE2   (SM_BE1 + 512)
#define SMEM_E   (SM_BE2 + 256)            // 197,  < 227KB

#define SM_BA1   (SM_B1 + 81920)           // kernel A
#define SM_WA2   (SM_BA1 + 512)
#define SM_PART  (SM_WA2 + 512)
#define SMEM_A   (SM_PART + 1024)

// ============================================================ helpers
union F2 { float2 f; unsigned long long u; };
__device__ __forceinline__ void fma2(F2& acc, F2 x, F2 w) {
    asm("fma.rn.f32x2 %0, %1, %2, %0;" : "+l"(acc.u) : "l"(x.u), "l"(w.u));
}
__device__ __forceinline__ void atomicMaxFloat(float* addr, float v) {
    if (v >= 0.0f) atomicMax((int*)addr, __float_as_int(v));
    else           atomicMin((unsigned int*)addr, __float_as_uint(v));
}
__device__ __forceinline__ uint32_t f2tf(float f) {
    uint32_t r; asm("cvt.rna.tf32.f32 %0, %1;" : "=r"(r) : "f"(f)); return r;
}
__device__ __forceinline__ float tfbits(float f) { return __uint_as_float(f2tf(f)); }

__device__ __forceinline__ void mma8(float* d, const uint32_t* a, const uint32_t* b) {
    asm volatile(
        "mma.sync.aligned.m16n8k8.row.col.f32.tf32.tf32.f32 "
        "{%0,%1,%2,%3}, {%4,%5,%6,%7}, {%8,%9}, {%0,%1,%2,%3};"
        : "+f"(d[0]), "+f"(d[1]), "+f"(d[2]), "+f"(d[3])
        : "r"(a[0]), "r"(a[1]), "r"(a[2]), "r"(a[3]), "r"(b[0]), "r"(b[1]));
}

// gather one 128-edge tile into A-fragment SoA planes (tf32 bits)
__device__ __forceinline__ void gather_tile(
    float* sx, const float* __restrict__ nf, const float* __restrict__ ef,
    const int* __restrict__ src, const int* __restrict__ dst, int tile, int tid)
{
    const int e_loc = tid >> 1, kh = tid & 1;
    const int e = tile * TILE + e_loc;
    const int s = src[e], d = dst[e];
    const int mt = e_loc >> 4, gid = e_loc & 7, hi = (e_loc >> 3) & 1;
    const float4* nfs = (const float4*)nf + (size_t)s * 16;
    const float4* nfd = (const float4*)nf + (size_t)d * 16;
    const float4* efe = (const float4*)ef + (size_t)e * 8;
    #pragma unroll
    for (int j = 0; j < 20; j++) {
        float4 v;
        if (kh == 0) v = (j < 16) ? nfs[j] : nfd[j - 16];
        else         v = (j < 12) ? nfd[4 + j] : efe[j - 12];
        const int kt = kh * 10 + (j >> 1);
        const int plane = hi + 2 * (j & 1);
        float* base = sx + plane * XPLANE + ((mt * 20 + kt) << 5) + (gid << 2);
        base[0] = tfbits(v.x); base[1] = tfbits(v.y);
        base[2] = tfbits(v.z); base[3] = tfbits(v.w);
    }
}

// pack a [K x N] row-major weight into m16n8k8 B-fragment layout (float2/lane)
__device__ __forceinline__ void pack_B(float* fb, const float* __restrict__ W,
                                       int K, int N, int tid, int nthr)
{
    for (int idx = tid; idx < K * N; idx += nthr) {
        const int k = idx / N, n = idx - k * N;
        const int a = (((k >> 3) * (N >> 3) + (n >> 3)) << 5) + ((n & 7) << 2) + (k & 3);
        fb[a * 2 + ((k >> 2) & 1)] = tfbits(W[idx]);
    }
}

// ============================================================
// K0: init scratch
// ============================================================
__global__ void init_kernel() {
    int idx = blockIdx.x * blockDim.x + threadIdx.x;
    g_agg[idx] = 0.0f;
    if (idx < NN) {
        g_m[idx] = __int_as_float(0xff800000);
        g_denom[idx] = 0.0f;
    }
}

// ============================================================
// K1a: edge-model MLP (persistent, tf32 mma.sync)
// ============================================================
__global__ __launch_bounds__(256, 1) void edgeE_kernel(
    const float* __restrict__ nf, const float* __restrict__ ef,
    const int* __restrict__ src, const int* __restrict__ dst,
    const float* __restrict__ We1, const float* __restrict__ be1,
    const float* __restrict__ We2, const float* __restrict__ be2,
    float* __restrict__ uh_e)
{
    extern __shared__ char smem[];
    float* sx   = (float*)(smem + SM_X);
    float* sB1  = (float*)(smem + SM_B1);
    float* sB2  = (float*)(smem + SM_B2);
    float* sbe1 = (float*)(smem + SM_BE1);
    float* sbe2 = (float*)(smem + SM_BE2);

    const int tid = threadIdx.x;
    const int w = tid >> 5, lane = tid & 31;
    const int wm = w & 3, wn = w >> 2;
    const int tig = lane & 3, gid = lane >> 2;

    pack_B(sB1, We1, EMIN, HID, tid, 256);
    pack_B(sB2, We2, HID, EOUT, tid, 256);
    if (tid < 128) sbe1[tid] = be1[tid];
    if (tid < 64)  sbe2[tid] = be2[tid];
    __syncthreads();

    const float2* B1f = (const float2*)sB1;
    const float2* B2f = (const float2*)sB2;

    for (int tile = blockIdx.x; tile < NTILES; tile += gridDim.x) {
        __syncthreads();
        gather_tile(sx, nf, ef, src, dst, tile, tid);
        __syncthreads();

        // ---- layer 1: [128e x 160k] x [160k x 128n] ----
        float acc[2][8][4];
        #pragma unroll
        for (int mi = 0; mi < 2; mi++)
            #pragma unroll
            for (int ni = 0; ni < 8; ni++)
                #pragma unroll
                for (int c = 0; c < 4; c++) acc[mi][ni][c] = 0.0f;

        #pragma unroll 2
        for (int kt = 0; kt < 20; kt++) {
            uint32_t a[2][4];
            #pragma unroll
            for (int mi = 0; mi < 2; mi++) {
                const int slot = (((2 * wm + mi) * 20 + kt) << 5) + lane;
                #pragma unroll
                for (int p = 0; p < 4; p++)
                    a[mi][p] = __float_as_uint(sx[p * XPLANE + slot]);
            }
            uint32_t b[8][2];
            #pragma unroll
            for (int ni = 0; ni < 8; ni++) {
                float2 t = B1f[((kt * 16 + wn * 8 + ni) << 5) + lane];
                b[ni][0] = __float_as_uint(t.x);
                b[ni][1] = __float_as_uint(t.y);
            }
            #pragma unroll
            for (int mi = 0; mi < 2; mi++)
                #pragma unroll
                for (int ni = 0; ni < 8; ni++)
                    mma8(acc[mi][ni], a[mi], b[ni]);
        }
        __syncthreads();

        // ---- relu+bias -> h fragments (alias over sx) ----
        float* sh = sx;
        #pragma unroll
        for (int mi = 0; mi < 2; mi++) {
            const int mt = 2 * wm + mi;
            #pragma unroll
            for (int ni = 0; ni < 8; ni++) {
                const int j0 = wn * 64 + ni * 8 + 2 * tig;
                const int jt = j0 >> 3;
                const int khalf = (j0 >> 2) & 1;
                const int t0 = j0 & 3, t1 = (j0 + 1) & 3;
                const float b0 = sbe1[j0], b1 = sbe1[j0 + 1];
                const int sbase = ((mt * 16 + jt) << 5) + (gid << 2);
                sh[(0 + 2 * khalf) * HPLANE + sbase + t0] = tfbits(fmaxf(acc[mi][ni][0] + b0, 0.f));
                sh[(0 + 2 * khalf) * HPLANE + sbase + t1] = tfbits(fmaxf(acc[mi][ni][1] + b1, 0.f));
                sh[(1 + 2 * khalf) * HPLANE + sbase + t0] = tfbits(fmaxf(acc[mi][ni][2] + b0, 0.f));
                sh[(1 + 2 * khalf) * HPLANE + sbase + t1] = tfbits(fmaxf(acc[mi][ni][3] + b1, 0.f));
            }
        }
        __syncthreads();

        // ---- layer 2: [128e x 128k] x [128k x 64n] ----
        float acc2[2][4][4];
        #pragma unroll
        for (int mi = 0; mi < 2; mi++)
            #pragma unroll
            for (int ni = 0; ni < 4; ni++)
                #pragma unroll
                for (int c = 0; c < 4; c++) acc2[mi][ni][c] = 0.0f;

        #pragma unroll 2
        for (int jt = 0; jt < 16; jt++) {
            uint32_t a[2][4];
            #pragma unroll
            for (int mi = 0; mi < 2; mi++) {
                const int slot = (((2 * wm + mi) * 16 + jt) << 5) + lane;
                #pragma unroll
                for (int p = 0; p < 4; p++)
                    a[mi][p] = __float_as_uint(sh[p * HPLANE + slot]);
            }
            uint32_t b[4][2];
            #pragma unroll
            for (int ni = 0; ni < 4; ni++) {
                float2 t = B2f[((jt * 8 + wn * 4 + ni) << 5) + lane];
                b[ni][0] = __float_as_uint(t.x);
                b[ni][1] = __float_as_uint(t.y);
            }
            #pragma unroll
            for (int mi = 0; mi < 2; mi++)
                #pragma unroll
                for (int ni = 0; ni < 4; ni++)
                    mma8(acc2[mi][ni], a[mi], b[ni]);
        }

        // ---- epilogue: bias + store uh_e ----
        #pragma unroll
        for (int mi = 0; mi < 2; mi++) {
            const int e0 = tile * TILE + wm * 32 + mi * 16 + gid;
            #pragma unroll
            for (int ni = 0; ni < 4; ni++) {
                const int o = wn * 32 + ni * 8 + 2 * tig;
                const float b0 = sbe2[o], b1 = sbe2[o + 1];
                float2 v0, v1;
                v0.x = acc2[mi][ni][0] + b0; v0.y = acc2[mi][ni][1] + b1;
                v1.x = acc2[mi][ni][2] + b0; v1.y = acc2[mi][ni][3] + b1;
                *(float2*)&uh_e[(size_t)e0 * EOUT + o] = v0;
                *(float2*)&uh_e[(size_t)(e0 + 8) * EOUT + o] = v1;
            }
        }
    }
}

// ============================================================
// K1b: attention MLP + logits (persistent, tf32 mma.sync)
// ============================================================
__global__ __launch_bounds__(256, 1) void edgeA_kernel(
    const float* __restrict__ nf, const float* __restrict__ ef,
    const int* __restrict__ src, const int* __restrict__ dst,
    const float* __restrict__ Wa1, const float* __restrict__ ba1,
    const float* __restrict__ Wa2, const float* __restrict__ ba2)
{
    extern __shared__ char smem[];
    float* sx    = (float*)(smem + SM_X);
    float* sB1   = (float*)(smem + SM_B1);
    float* sba1  = (float*)(smem + SM_BA1);
    float* swa2  = (float*)(smem + SM_WA2);
    float* spart = (float*)(smem + SM_PART);

    const int tid = threadIdx.x;
    const int w = tid >> 5, lane = tid & 31;
    const int wm = w & 3, wn = w >> 2;
    const int tig = lane & 3, gid = lane >> 2;

    pack_B(sB1, Wa1, EMIN, HID, tid, 256);
    if (tid < 128) { sba1[tid] = ba1[tid]; swa2[tid] = Wa2[tid]; }
    const float ba2v = ba2[0];
    __syncthreads();

    const float2* B1f = (const float2*)sB1;

    for (int tile = blockIdx.x; tile < NTILES; tile += gridDim.x) {
        __syncthreads();
        gather_tile(sx, nf, ef, src, dst, tile, tid);
        __syncthreads();

        float acc[2][8][4];
        #pragma unroll
        for (int mi = 0; mi < 2; mi++)
            #pragma unroll
            for (int ni = 0; ni < 8; ni++)
                #pragma unroll
                for (int c = 0; c < 4; c++) acc[mi][ni][c] = 0.0f;

        #pragma unroll 2
        for (int kt = 0; kt < 20; kt++) {
            uint32_t a[2][4];
            #pragma unroll
            for (int mi = 0; mi < 2; mi++) {
                const int slot = (((2 * wm + mi) * 20 + kt) << 5) + lane;
                #pragma unroll
                for (int p = 0; p < 4; p++)
                    a[mi][p] = __float_as_uint(sx[p * XPLANE + slot]);
            }
            uint32_t b[8][2];
            #pragma unroll
            for (int ni = 0; ni < 8; ni++) {
                float2 t = B1f[((kt * 16 + wn * 8 + ni) << 5) + lane];
                b[ni][0] = __float_as_uint(t.x);
                b[ni][1] = __float_as_uint(t.y);
            }
            #pragma unroll
            for (int mi = 0; mi < 2; mi++)
                #pragma unroll
                for (int ni = 0; ni < 8; ni++)
                    mma8(acc[mi][ni], a[mi], b[ni]);
        }

        // ---- logit = sum_j relu(h+b)*wa2[j], reduced in-register ----
        float part[2][2] = {{0.f, 0.f}, {0.f, 0.f}};
        #pragma unroll
        for (int ni = 0; ni < 8; ni++) {
            const int j0 = wn * 64 + ni * 8 + 2 * tig;
            const float w0 = swa2[j0], w1 = swa2[j0 + 1];
            const float b0 = sba1[j0], b1 = sba1[j0 + 1];
            #pragma unroll
            for (int mi = 0; mi < 2; mi++) {
                part[mi][0] += fmaxf(acc[mi][ni][0] + b0, 0.f) * w0
                             + fmaxf(acc[mi][ni][1] + b1, 0.f) * w1;
                part[mi][1] += fmaxf(acc[mi][ni][2] + b0, 0.f) * w0
                             + fmaxf(acc[mi][ni][3] + b1, 0.f) * w1;
            }
        }
        #pragma unroll
        for (int mi = 0; mi < 2; mi++)
            #pragma unroll
            for (int h2 = 0; h2 < 2; h2++) {
                float v = part[mi][h2];
                v += __shfl_xor_sync(0xffffffff, v, 1);
                v += __shfl_xor_sync(0xffffffff, v, 2);
                if (tig == 0)
                    spart[wn * 128 + wm * 32 + mi * 16 + h2 * 8 + gid] = v;
            }
        __syncthreads();
        if (tid < 128) {
            const int e = tile * TILE + tid;
            const float logit = spart[tid] + spart[128 + tid] + ba2v;
            g_logits[e] = logit;
            atomicMaxFloat(&g_m[dst[e]], logit);
        }
    }
}

// ============================================================
// K2: ex = exp(logit - m[dst]); denom[dst] += ex
// ============================================================
__global__ void softmax_kernel(const int* __restrict__ dst) {
    int e = blockIdx.x * blockDim.x + threadIdx.x;
    int d = dst[e];
    float ex = expf(g_logits[e] - g_m[d]);
    g_ex[e] = ex;
    atomicAdd(&g_denom[d], ex);
}

// ============================================================
// K3: agg[dst] += uh_e * attn (vector red.v4)
// ============================================================
__global__ void agg_kernel(const int* __restrict__ dst,
                           const float* __restrict__ uh_e) {
    size_t idx = (size_t)blockIdx.x * blockDim.x + threadIdx.x;
    int e  = (int)(idx >> 4);
    int jq = (int)(idx & 15);
    int d  = dst[e];
    float w = g_ex[e] / fmaxf(g_denom[d], 1e-38f);
    float4 v = ((const float4*)uh_e)[(size_t)e * 16 + jq];
    v.x *= w; v.y *= w; v.z *= w; v.w *= w;
    float* p = &g_agg[(size_t)d * EOUT + jq * 4];
    asm volatile("red.global.add.v4.f32 [%0], {%1, %2, %3, %4};"
                 :: "l"(p), "f"(v.x), "f"(v.y), "f"(v.z), "f"(v.w) : "memory");
}

// ============================================================
// K4: node MLP (scalar f32x2 path, known good)
// ============================================================
__global__ __launch_bounds__(128) void node_kernel(
    const float* __restrict__ nf,
    const float* __restrict__ Wn1, const float* __restrict__ bn1,
    const float* __restrict__ Wn2, const float* __restrict__ bn2,
    float* __restrict__ uh_n)
{
    __shared__ float s_x[NMIN * PITCH];

    const int tid = threadIdx.x;
    const int n0  = blockIdx.x * TE;

    {
        const int e  = tid & 31;
        const int kq = tid >> 5;
        const int n  = n0 + e;
        const bool ok = (n < NN);
        const float4* ag4 = (const float4*)g_agg;
        const float4* nf4 = (const float4*)nf;
        #pragma unroll
        for (int kk = kq; kk < 32; kk += 4) {
            float4 v = make_float4(0.f, 0.f, 0.f, 0.f);
            if (ok) {
                if (kk < 16) v = ag4[(size_t)n * 16 + kk];
                else         v = nf4[(size_t)n * 16 + (kk - 16)];
            }
            const int k = kk * 4;
            s_x[(k + 0) * PITCH + e] = v.x;
            s_x[(k + 1) * PITCH + e] = v.y;
            s_x[(k + 2) * PITCH + e] = v.z;
            s_x[(k + 3) * PITCH + e] = v.w;
        }
    }
    __syncthreads();

    F2 h[16];
    {
        float b = bn1[tid];
        #pragma unroll
        for (int i = 0; i < 16; i++) h[i].f = make_float2(b, b);
    }
    #pragma unroll 2
    for (int k = 0; k < NMIN; k++) {
        const float w1 = __ldg(&Wn1[k * HID + tid]);
        F2 w; w.f = make_float2(w1, w1);
        const float* row = &s_x[k * PITCH];
        #pragma unroll
        for (int i = 0; i < 16; i++) {
            F2 x; x.f = *(const float2*)&row[2 * i];
            fma2(h[i], x, w);
        }
    }
    __syncthreads();
    float* s_h = s_x;
    #pragma unroll
    for (int i = 0; i < 16; i++) {
        float2 v = h[i].f;
        v.x = fmaxf(v.x, 0.0f); v.y = fmaxf(v.y, 0.0f);
        *(float2*)&s_h[tid * PITCH + 2 * i] = v;
    }
    __syncthreads();

    {
        const int o     = tid & 63;
        const int half  = tid >> 6;
        const int ebase = half * 16;
        F2 acc[8];
        const float b2 = bn2[o];
        #pragma unroll
        for (int i = 0; i < 8; i++) acc[i].f = make_float2(b2, b2);

        #pragma unroll 2
        for (int j = 0; j < HID; j++) {
            const float w = __ldg(&Wn2[j * DOUT + o]);
            F2 w2; w2.f = make_float2(w, w);
            const float* row = &s_h[j * PITCH + ebase];
            #pragma unroll
            for (int i = 0; i < 8; i++) {
                F2 x; x.f = *(const float2*)&row[2 * i];
                fma2(acc[i], x, w2);
            }
        }
        #pragma unroll
        for (int i = 0; i < 8; i++) {
            int na = n0 + ebase + 2 * i;
            int nb = na + 1;
            if (na < NN) uh_n[(size_t)na * DOUT + o] = acc[i].f.x;
            if (nb < NN) uh_n[(size_t)nb * DOUT + o] = acc[i].f.y;
        }
    }
}

// ============================================================
extern "C" void kernel_launch(void* const* d_in, const int* in_sizes, int n_in,
                              void* d_out, int out_size) {
    const float* nf  = (const float*)d_in[0];
    const float* ef  = (const float*)d_in[1];
    const int*   src = (const int*)d_in[2];
    const int*   dst = (const int*)d_in[3];
    const float* We1 = (const float*)d_in[4];
    const float* be1 = (const float*)d_in[5];
    const float* We2 = (const float*)d_in[6];
    const float* be2 = (const float*)d_in[7];
    const float* Wa1 = (const float*)d_in[8];
    const float* ba1 = (const float*)d_in[9];
    const float* Wa2 = (const float*)d_in[10];
    const float* ba2 = (const float*)d_in[11];
    const float* Wn1 = (const float*)d_in[12];
    const float* bn1 = (const float*)d_in[13];
    const float* Wn2 = (const float*)d_in[14];
    const float* bn2 = (const float*)d_in[15];

    float* out  = (float*)d_out;
    float* uh_n = out;
    float* uh_e = out + (size_t)NN * DOUT;

    static bool attr_set = false;
    if (!attr_set) {
        cudaFuncSetAttribute(edgeE_kernel, cudaFuncAttributeMaxDynamicSharedMemorySize, SMEM_E);
        cudaFuncSetAttribute(edgeA_kernel, cudaFuncAttributeMaxDynamicSharedMemorySize, SMEM_A);
        attr_set = true;
    }

    init_kernel<<<(NN * 64) / 256, 256>>>();
    edgeE_kernel<<<GRID_P, 256, SMEM_E>>>(nf, ef, src, dst, We1, be1, We2, be2, uh_e);
    edgeA_kernel<<<GRID_P, 256, SMEM_A>>>(nf, ef, src, dst, Wa1, ba1, Wa2, ba2);
    softmax_kernel<<<E_TOTAL / 256, 256>>>(dst);
    agg_kernel<<<(E_TOTAL * 16) / 256, 256>>>(dst, uh_e);
    node_kernel<<<(NN + TE - 1) / TE, 128>>>(nf, Wn1, bn1, Wn2, bn2, uh_n);
}